// round 9
// baseline (speedup 1.0000x reference)
#include <cuda_runtime.h>
#include <cuda_fp16.h>
#include <math.h>
#include <stdint.h>

#define NTOK 8192
#define DDIM 1024
#define HDIM 4096
#define NEXP 8
#define CAP  2048
#define NENT (2*NTOK)

#define STAGES 3
#define STAGE_BYTES 32768          // A 16KB (128m x 64k) + B 16KB (64k x 128n), fp16
#define DSMEM_BYTES (STAGES*STAGE_BYTES + 1024)

#define CONV_BLOCKS 512
#define WELEMS ((size_t)NEXP*DDIM*HDIM)
#define WQUADS (WELEMS/4)
#define QPB    (WQUADS/CONV_BLOCKS)
#define QPT    (QPB/256)

// ---------------- scratch (device globals; no allocation allowed) ----------------
__device__ __half g_disp[(size_t)NEXP*CAP*DDIM];   // 32 MB
__device__ __half g_h[(size_t)NEXP*CAP*HDIM];      // 128 MB
__device__ float  g_y0[(size_t)NEXP*CAP*DDIM];     // 64 MB split-K partial ks=0
__device__ float  g_y1[(size_t)NEXP*CAP*DDIM];     // 64 MB split-K partial ks=1
__device__ __half g_w1h[WELEMS];                   // 64 MB
__device__ __half g_w2h[WELEMS];                   // 64 MB
__device__ int    g_eid[NENT];
__device__ float  g_gv[NENT];
__device__ int    g_pos[NENT];

// ---------------- helpers ----------------
__device__ __forceinline__ uint32_t s2u(const void* p) {
    uint32_t a;
    asm("{ .reg .u64 t; cvta.to.shared.u64 t, %1; cvt.u32.u64 %0, t; }" : "=r"(a) : "l"(p));
    return a;
}
__device__ __forceinline__ void cpasync16(uint32_t dst, const void* src) {
    asm volatile("cp.async.cg.shared.global [%0], [%1], 16;" :: "r"(dst), "l"(src));
}
__device__ __forceinline__ void cp_commit() { asm volatile("cp.async.commit_group;" ::: "memory"); }
template<int N> __device__ __forceinline__ void cp_wait() {
    asm volatile("cp.async.wait_group %0;" :: "n"(N) : "memory");
}
__device__ __forceinline__ void ldsm4(uint32_t* d, uint32_t addr) {
    asm volatile("ldmatrix.sync.aligned.m8n8.x4.shared.b16 {%0,%1,%2,%3}, [%4];"
        : "=r"(d[0]), "=r"(d[1]), "=r"(d[2]), "=r"(d[3]) : "r"(addr));
}
__device__ __forceinline__ void ldsm4t(uint32_t* d, uint32_t addr) {
    asm volatile("ldmatrix.sync.aligned.m8n8.x4.trans.shared.b16 {%0,%1,%2,%3}, [%4];"
        : "=r"(d[0]), "=r"(d[1]), "=r"(d[2]), "=r"(d[3]) : "r"(addr));
}
__device__ __forceinline__ void mma16816(float* d, const uint32_t* a, const uint32_t* b) {
    asm volatile(
        "mma.sync.aligned.m16n8k16.row.col.f32.f16.f16.f32 "
        "{%0,%1,%2,%3}, {%4,%5,%6,%7}, {%8,%9}, {%0,%1,%2,%3};"
        : "+f"(d[0]), "+f"(d[1]), "+f"(d[2]), "+f"(d[3])
        : "r"(a[0]), "r"(a[1]), "r"(a[2]), "r"(a[3]), "r"(b[0]), "r"(b[1]));
}
__device__ __forceinline__ float gelu_exact(float v) {
    return 0.5f * v * (1.f + erff(v * 0.70710678118654752f));
}
__device__ __forceinline__ void conv_chunk(const float* __restrict__ W,
                                           __half* __restrict__ Wh,
                                           int bid, int tid) {
    size_t base = (size_t)bid * QPB;
#pragma unroll 4
    for (int j = 0; j < QPT; j++) {
        size_t i = base + (size_t)j * 256 + tid;
        const float4 v = ((const float4*)W)[i];
        __half2* o = (__half2*)Wh + i * 2;
        o[0] = __floats2half2_rn(v.x, v.y);
        o[1] = __floats2half2_rn(v.z, v.w);
    }
}

// ---------------- gate ----------------
__global__ void gate_kernel(const float* __restrict__ x, const float* __restrict__ wg) {
    __shared__ float wsh[NEXP*DDIM];
    int tid = threadIdx.x;
    for (int i = tid; i < NEXP*DDIM; i += 256) {
        int d = i / NEXP, e = i % NEXP;
        wsh[e*DDIM + d] = wg[i];
    }
    __syncthreads();
    int warp = tid >> 5, lane = tid & 31;
    int n = blockIdx.x * 8 + warp;
    const float* xr = x + (size_t)n * DDIM;
    float acc[NEXP];
#pragma unroll
    for (int e = 0; e < NEXP; e++) acc[e] = 0.f;
    for (int d = lane; d < DDIM; d += 32) {
        float xv = xr[d];
#pragma unroll
        for (int e = 0; e < NEXP; e++) acc[e] += xv * wsh[e*DDIM + d];
    }
#pragma unroll
    for (int e = 0; e < NEXP; e++) {
#pragma unroll
        for (int off = 16; off; off >>= 1)
            acc[e] += __shfl_xor_sync(0xffffffffu, acc[e], off);
    }
    if (lane == 0) {
        float l0 = -1e30f; int i0 = 0;
#pragma unroll
        for (int e = 0; e < NEXP; e++) if (acc[e] > l0) { l0 = acc[e]; i0 = e; }
        float l1 = -1e30f; int i1 = 0;
#pragma unroll
        for (int e = 0; e < NEXP; e++) if (e != i0 && acc[e] > l1) { l1 = acc[e]; i1 = e; }
        float r  = expf(l1 - l0);
        float g0 = 1.f / (1.f + r);
        g_eid[n]        = i0;
        g_eid[NTOK + n] = i1;
        g_gv[n]         = g0;
        g_gv[NTOK + n]  = 1.f - g0;
    }
}

// ---------------- GShard capacity positions ----------------
__global__ void pos_kernel() {
    __shared__ int cnt[1024][NEXP];
    int t = threadIdx.x;
    int base = t * 16;
#pragma unroll
    for (int e = 0; e < NEXP; e++) cnt[t][e] = 0;
    for (int j = 0; j < 16; j++) cnt[t][g_eid[base + j]]++;
    __syncthreads();
    if (t < 256) {
        int w = t >> 5, lane = t & 31;
        int s = 0;
        for (int j = 0; j < 32; j++) s += cnt[lane*32 + j][w];
        int incl = s;
#pragma unroll
        for (int off = 1; off < 32; off <<= 1) {
            int v = __shfl_up_sync(0xffffffffu, incl, off);
            if (lane >= off) incl += v;
        }
        int run = incl - s;
        for (int j = 0; j < 32; j++) {
            int v = cnt[lane*32 + j][w];
            cnt[lane*32 + j][w] = run;
            run += v;
        }
    }
    __syncthreads();
    for (int j = 0; j < 16; j++) {
        int i = base + j;
        int e = g_eid[i];
        int p = cnt[t][e]++;
        if (p < CAP) {
            g_pos[i] = p;
        } else {
            g_pos[i] = -1;
            g_gv[i]  = 0.f;
        }
    }
}

// ---------------- dispatch scatter (f32 -> fp16) + fused w1 convert ----------------
__global__ void dispatch_kernel(const float* __restrict__ x,
                                const float* __restrict__ w1) {
    int i = blockIdx.x;
    if (i >= NENT) {
        conv_chunk(w1, g_w1h, i - NENT, threadIdx.x);
        return;
    }
    int p = g_pos[i];
    if (p < 0) return;
    int e = g_eid[i];
    int n = i & (NTOK - 1);
    const float4 v = ((const float4*)(x + (size_t)n * DDIM))[threadIdx.x];
    __half2* dst = (__half2*)(g_disp + (size_t)(e*CAP + p) * DDIM) + threadIdx.x * 2;
    dst[0] = __floats2half2_rn(v.x, v.y);
    dst[1] = __floats2half2_rn(v.z, v.w);
}

// ---------------- fp16 mma GEMM ----------------
// CTA 128x128, BK=64, 3-stage cp.async, 8 warps (4m x 2n), warp tile 32x64.
// MODE 0 (gemm1): C = GELU(A*B+bias) -> fp16 Cb; grid.z==NEXP blocks convert w2.
// MODE 1 (gemm2 split-K=2): z = e*2+ks; computes K half [ks*KLEN,(ks+1)*KLEN);
//   plain float2 stores of partial (+bias iff ks==0) into g_y0 (ks=0) / g_y1 (ks=1).
template<int KSTRIDE, int KLEN, int NDIM, int MODE>
__global__ void __launch_bounds__(256, 2)
gemm_mma(const __half* __restrict__ Abase, const __half* __restrict__ Bbase,
         const float* __restrict__ biasb, void* __restrict__ Cb,
         const float* __restrict__ Wsrc, __half* __restrict__ Wdst) {
    extern __shared__ char dynsm[];
    int tid = threadIdx.x;

    if (MODE == 0 && blockIdx.z == NEXP) {
        int bid = blockIdx.y * gridDim.x + blockIdx.x;
        conv_chunk(Wsrc, Wdst, bid, tid);
        return;
    }

    uint32_t sbase = (s2u(dynsm) + 1023u) & ~1023u;
    int lane = tid & 31, warp = tid >> 5;
    int e, ks;
    if (MODE == 1) { e = blockIdx.z >> 1; ks = blockIdx.z & 1; }
    else           { e = blockIdx.z;      ks = 0; }
    int bm = blockIdx.y * 128, bn = blockIdx.x * 128;
    const __half* A = Abase + (size_t)e * CAP * KSTRIDE + (size_t)bm * KSTRIDE
                    + (size_t)ks * KLEN;
    const __half* B = Bbase + (size_t)e * KSTRIDE * NDIM + (size_t)ks * KLEN * NDIM + bn;
    const float* bias = biasb + (size_t)e * NDIM + bn;

    constexpr int KT = KLEN / 64;

    int wm = (warp >> 1) * 32;
    int wn = (warp & 1) * 64;
    int r8 = lane & 7, t4 = lane >> 3;

    float acc[2][8][4];
#pragma unroll
    for (int mi = 0; mi < 2; mi++)
#pragma unroll
        for (int ni = 0; ni < 8; ni++)
#pragma unroll
            for (int q = 0; q < 4; q++) acc[mi][ni][q] = 0.f;

    auto load_stage = [&](int kt) {
        uint32_t sa = sbase + (uint32_t)(kt % STAGES) * STAGE_BYTES;
        uint32_t sb = sa + 16384;
        const __half* Ap = A + kt * 64;
        const __half* Bp = B + (size_t)(kt * 64) * NDIM;
#pragma unroll
        for (int i = 0; i < 4; i++) {
            int idx = i * 256 + tid;
            int row = idx >> 3, c = idx & 7;
            cpasync16(sa + (uint32_t)(row * 128 + ((c ^ (row & 7)) << 4)),
                      Ap + (size_t)row * KSTRIDE + c * 8);
        }
#pragma unroll
        for (int i = 0; i < 4; i++) {
            int idx = i * 256 + tid;
            int row = idx >> 4, c = idx & 15;
            cpasync16(sb + (uint32_t)(row * 256 + ((c ^ (row & 7)) << 4)),
                      Bp + (size_t)row * NDIM + c * 8);
        }
    };

#pragma unroll
    for (int kt = 0; kt < STAGES - 1; kt++) { load_stage(kt); cp_commit(); }

    for (int kt = 0; kt < KT; kt++) {
        cp_wait<STAGES - 2>();
        __syncthreads();

        int ktp = kt + STAGES - 1;
        if (ktp < KT) load_stage(ktp);
        cp_commit();

        uint32_t sA = sbase + (uint32_t)(kt % STAGES) * STAGE_BYTES;
        uint32_t sB = sA + 16384;
#pragma unroll
        for (int ks4 = 0; ks4 < 4; ks4++) {
            int kc = ks4 * 2;
            uint32_t a[2][4], b[8][2];
#pragma unroll
            for (int mi = 0; mi < 2; mi++) {
                int row = wm + mi * 16 + (t4 & 1) * 8 + r8;
                int cc  = kc + (t4 >> 1);
                ldsm4(a[mi], sA + (uint32_t)(row * 128 + ((cc ^ (row & 7)) << 4)));
            }
#pragma unroll
            for (int nj = 0; nj < 4; nj++) {
                int krow = ks4 * 16 + (lane & 15);
                int c    = ((wn + nj * 16) >> 3) + (lane >> 4);
                uint32_t q[4];
                ldsm4t(q, sB + (uint32_t)(krow * 256 + ((c ^ (krow & 7)) << 4)));
                b[2*nj][0]   = q[0]; b[2*nj][1]   = q[1];
                b[2*nj+1][0] = q[2]; b[2*nj+1][1] = q[3];
            }
#pragma unroll
            for (int mi = 0; mi < 2; mi++)
#pragma unroll
                for (int ni = 0; ni < 8; ni++)
                    mma16816(acc[mi][ni], a[mi], b[ni]);
        }
    }

    // epilogue
    int grp = lane >> 2, tig = lane & 3;
    if (MODE == 0) {
        __half* Ce = (__half*)Cb + (size_t)e * CAP * NDIM;
#pragma unroll
        for (int mi = 0; mi < 2; mi++) {
#pragma unroll
            for (int ni = 0; ni < 8; ni++) {
                int row = bm + wm + mi * 16 + grp;
                int col = bn + wn + ni * 8 + tig * 2;
                float b0  = bias[wn + ni * 8 + tig * 2];
                float b1v = bias[wn + ni * 8 + tig * 2 + 1];
                float v0 = gelu_exact(acc[mi][ni][0] + b0);
                float v1 = gelu_exact(acc[mi][ni][1] + b1v);
                float v2 = gelu_exact(acc[mi][ni][2] + b0);
                float v3 = gelu_exact(acc[mi][ni][3] + b1v);
                *(__half2*)(Ce + (size_t)row * NDIM + col) = __floats2half2_rn(v0, v1);
                *(__half2*)(Ce + (size_t)(row + 8) * NDIM + col) = __floats2half2_rn(v2, v3);
            }
        }
    } else {
        float* Ce = (ks == 0 ? g_y0 : g_y1) + (size_t)e * CAP * NDIM;
        float bs = (ks == 0) ? 1.f : 0.f;
#pragma unroll
        for (int mi = 0; mi < 2; mi++) {
#pragma unroll
            for (int ni = 0; ni < 8; ni++) {
                int row = bm + wm + mi * 16 + grp;
                int col = bn + wn + ni * 8 + tig * 2;
                float b0  = bs * bias[wn + ni * 8 + tig * 2];
                float b1v = bs * bias[wn + ni * 8 + tig * 2 + 1];
                *(float2*)(Ce + (size_t)row * NDIM + col) =
                    make_float2(acc[mi][ni][0] + b0, acc[mi][ni][1] + b1v);
                *(float2*)(Ce + (size_t)(row + 8) * NDIM + col) =
                    make_float2(acc[mi][ni][2] + b0, acc[mi][ni][3] + b1v);
            }
        }
    }
}

// ---------------- combine (sum split-K partials, gate-weighted) ----------------
__global__ void combine_kernel(float* __restrict__ out) {
    int n = blockIdx.x;
    int t = threadIdx.x;
    float4 acc = make_float4(0.f, 0.f, 0.f, 0.f);
#pragma unroll
    for (int kk = 0; kk < 2; kk++) {
        int i = kk * NTOK + n;
        int p = g_pos[i];
        if (p >= 0) {
            float g = g_gv[i];
            size_t off = (size_t)(g_eid[i]*CAP + p) * DDIM;
            const float4 v0 = *((const float4*)(g_y0 + off) + t);
            const float4 v1 = *((const float4*)(g_y1 + off) + t);
            acc.x += g * (v0.x + v1.x); acc.y += g * (v0.y + v1.y);
            acc.z += g * (v0.z + v1.z); acc.w += g * (v0.w + v1.w);
        }
    }
    ((float4*)out)[(size_t)n * 256 + t] = acc;
}

// ---------------- launch ----------------
extern "C" void kernel_launch(void* const* d_in, const int* in_sizes, int n_in,
                              void* d_out, int out_size) {
    const float* x  = (const float*)d_in[0];
    const float* wg = (const float*)d_in[1];
    const float* w1 = (const float*)d_in[2];
    const float* b1 = (const float*)d_in[3];
    const float* w2 = (const float*)d_in[4];
    const float* b2 = (const float*)d_in[5];
    float* out = (float*)d_out;

    static int attr_done = 0;
    if (!attr_done) {
        cudaFuncSetAttribute(gemm_mma<DDIM, DDIM, HDIM, 0>,
                             cudaFuncAttributeMaxDynamicSharedMemorySize, DSMEM_BYTES);
        cudaFuncSetAttribute(gemm_mma<HDIM, HDIM/2, DDIM, 1>,
                             cudaFuncAttributeMaxDynamicSharedMemorySize, DSMEM_BYTES);
        attr_done = 1;
    }

    __half* w1h;  cudaGetSymbolAddress((void**)&w1h,  g_w1h);
    __half* w2h;  cudaGetSymbolAddress((void**)&w2h,  g_w2h);
    __half* disp; cudaGetSymbolAddress((void**)&disp, g_disp);
    __half* hbuf; cudaGetSymbolAddress((void**)&hbuf, g_h);

    gate_kernel<<<NTOK/8, 256>>>(x, wg);
    pos_kernel<<<1, 1024>>>();
    dispatch_kernel<<<NENT + CONV_BLOCKS, 256>>>(x, w1);
    gemm_mma<DDIM, DDIM, HDIM, 0>
        <<<dim3(HDIM/128, CAP/128, NEXP + 1), 256, DSMEM_BYTES>>>(
        disp, w1h, b1, hbuf, w2, w2h);
    gemm_mma<HDIM, HDIM/2, DDIM, 1>
        <<<dim3(DDIM/128, CAP/128, NEXP*2), 256, DSMEM_BYTES>>>(
        hbuf, w2h, b2, nullptr, nullptr, nullptr);
    combine_kernel<<<NTOK, 256>>>(out);
}

// round 10
// speedup vs baseline: 1.0399x; 1.0399x over previous
#include <cuda_runtime.h>
#include <cuda_fp16.h>
#include <math.h>
#include <stdint.h>

#define NTOK 8192
#define DDIM 1024
#define HDIM 4096
#define NEXP 8
#define CAP  2048
#define NENT (2*NTOK)

#define STAGES 3
#define STAGE_BYTES 32768          // A 16KB (128m x 64k) + B 16KB (64k x 128n), fp16
#define DSMEM_BYTES (STAGES*STAGE_BYTES + 1024)

#define CONV_UNITS 512
#define WELEMS ((size_t)NEXP*DDIM*HDIM)
#define WQUADS (WELEMS/4)                    // 8,388,608 float4
#define QPB    (WQUADS/CONV_UNITS)           // 16384 float4 per unit
// w1 conv split: units [0,256) in gate grid, [256,512) in pos grid
#define GATE_CONV 256
#define POS_CONV_BLOCKS 64                   // 1024-thread blocks, 4 units each

// ---------------- scratch (device globals; no allocation allowed) ----------------
__device__ __half g_disp[(size_t)NEXP*CAP*DDIM];   // 32 MB
__device__ __half g_h[(size_t)NEXP*CAP*HDIM];      // 128 MB
__device__ float  g_y[(size_t)NEXP*CAP*DDIM];      // 64 MB
__device__ __half g_w1h[WELEMS];                   // 64 MB
__device__ __half g_w2h[WELEMS];                   // 64 MB
__device__ int    g_eid[NENT];
__device__ float  g_gv[NENT];
__device__ int    g_pos[NENT];

// ---------------- helpers ----------------
__device__ __forceinline__ uint32_t s2u(const void* p) {
    uint32_t a;
    asm("{ .reg .u64 t; cvta.to.shared.u64 t, %1; cvt.u32.u64 %0, t; }" : "=r"(a) : "l"(p));
    return a;
}
__device__ __forceinline__ void cpasync16(uint32_t dst, const void* src) {
    asm volatile("cp.async.cg.shared.global [%0], [%1], 16;" :: "r"(dst), "l"(src));
}
__device__ __forceinline__ void cp_commit() { asm volatile("cp.async.commit_group;" ::: "memory"); }
template<int N> __device__ __forceinline__ void cp_wait() {
    asm volatile("cp.async.wait_group %0;" :: "n"(N) : "memory");
}
__device__ __forceinline__ void ldsm4(uint32_t* d, uint32_t addr) {
    asm volatile("ldmatrix.sync.aligned.m8n8.x4.shared.b16 {%0,%1,%2,%3}, [%4];"
        : "=r"(d[0]), "=r"(d[1]), "=r"(d[2]), "=r"(d[3]) : "r"(addr));
}
__device__ __forceinline__ void ldsm4t(uint32_t* d, uint32_t addr) {
    asm volatile("ldmatrix.sync.aligned.m8n8.x4.trans.shared.b16 {%0,%1,%2,%3}, [%4];"
        : "=r"(d[0]), "=r"(d[1]), "=r"(d[2]), "=r"(d[3]) : "r"(addr));
}
__device__ __forceinline__ void mma16816(float* d, const uint32_t* a, const uint32_t* b) {
    asm volatile(
        "mma.sync.aligned.m16n8k16.row.col.f32.f16.f16.f32 "
        "{%0,%1,%2,%3}, {%4,%5,%6,%7}, {%8,%9}, {%0,%1,%2,%3};"
        : "+f"(d[0]), "+f"(d[1]), "+f"(d[2]), "+f"(d[3])
        : "r"(a[0]), "r"(a[1]), "r"(a[2]), "r"(a[3]), "r"(b[0]), "r"(b[1]));
}
__device__ __forceinline__ float gelu_exact(float v) {
    return 0.5f * v * (1.f + erff(v * 0.70710678118654752f));
}
// convert `units` consecutive QPB-sized chunks starting at unit `u0`,
// with `nthr` threads (tid in [0,nthr))
__device__ __forceinline__ void conv_units(const float* __restrict__ W,
                                           __half* __restrict__ Wh,
                                           int u0, int units, int tid, int nthr) {
    size_t base = (size_t)u0 * QPB;
    size_t count = (size_t)units * QPB;
    for (size_t j = tid; j < count; j += nthr) {
        size_t i = base + j;
        const float4 v = ((const float4*)W)[i];
        __half2* o = (__half2*)Wh + i * 2;
        o[0] = __floats2half2_rn(v.x, v.y);
        o[1] = __floats2half2_rn(v.z, v.w);
    }
}

// ---------------- gate (+ w1 convert units [0,GATE_CONV)) ----------------
__global__ void gate_kernel(const float* __restrict__ x, const float* __restrict__ wg,
                            const float* __restrict__ w1) {
    if (blockIdx.x >= NTOK/8) {
        conv_units(w1, g_w1h, blockIdx.x - NTOK/8, 1, threadIdx.x, 256);
        return;
    }
    __shared__ float wsh[NEXP*DDIM];
    int tid = threadIdx.x;
    for (int i = tid; i < NEXP*DDIM; i += 256) {
        int d = i / NEXP, e = i % NEXP;
        wsh[e*DDIM + d] = wg[i];
    }
    __syncthreads();
    int warp = tid >> 5, lane = tid & 31;
    int n = blockIdx.x * 8 + warp;
    const float* xr = x + (size_t)n * DDIM;
    float acc[NEXP];
#pragma unroll
    for (int e = 0; e < NEXP; e++) acc[e] = 0.f;
    for (int d = lane; d < DDIM; d += 32) {
        float xv = xr[d];
#pragma unroll
        for (int e = 0; e < NEXP; e++) acc[e] += xv * wsh[e*DDIM + d];
    }
#pragma unroll
    for (int e = 0; e < NEXP; e++) {
#pragma unroll
        for (int off = 16; off; off >>= 1)
            acc[e] += __shfl_xor_sync(0xffffffffu, acc[e], off);
    }
    if (lane == 0) {
        float l0 = -1e30f; int i0 = 0;
#pragma unroll
        for (int e = 0; e < NEXP; e++) if (acc[e] > l0) { l0 = acc[e]; i0 = e; }
        float l1 = -1e30f; int i1 = 0;
#pragma unroll
        for (int e = 0; e < NEXP; e++) if (e != i0 && acc[e] > l1) { l1 = acc[e]; i1 = e; }
        float r  = expf(l1 - l0);
        float g0 = 1.f / (1.f + r);
        g_eid[n]        = i0;
        g_eid[NTOK + n] = i1;
        g_gv[n]         = g0;
        g_gv[NTOK + n]  = 1.f - g0;
    }
}

// ---------------- GShard capacity positions (block 0) + w1 convert [GATE_CONV,512) ----------------
__global__ void pos_kernel(const float* __restrict__ w1) {
    if (blockIdx.x > 0) {
        conv_units(w1, g_w1h, GATE_CONV + (blockIdx.x - 1) * 4, 4, threadIdx.x, 1024);
        return;
    }
    __shared__ int cnt[1024][NEXP];
    int t = threadIdx.x;
    int base = t * 16;
#pragma unroll
    for (int e = 0; e < NEXP; e++) cnt[t][e] = 0;
    for (int j = 0; j < 16; j++) cnt[t][g_eid[base + j]]++;
    __syncthreads();
    if (t < 256) {
        int w = t >> 5, lane = t & 31;
        int s = 0;
        for (int j = 0; j < 32; j++) s += cnt[lane*32 + j][w];
        int incl = s;
#pragma unroll
        for (int off = 1; off < 32; off <<= 1) {
            int v = __shfl_up_sync(0xffffffffu, incl, off);
            if (lane >= off) incl += v;
        }
        int run = incl - s;
        for (int j = 0; j < 32; j++) {
            int v = cnt[lane*32 + j][w];
            cnt[lane*32 + j][w] = run;
            run += v;
        }
    }
    __syncthreads();
    for (int j = 0; j < 16; j++) {
        int i = base + j;
        int e = g_eid[i];
        int p = cnt[t][e]++;
        if (p < CAP) {
            g_pos[i] = p;
        } else {
            g_pos[i] = -1;
            g_gv[i]  = 0.f;
        }
    }
}

// ---------------- dispatch scatter (f32 -> fp16) ----------------
__global__ void dispatch_kernel(const float* __restrict__ x) {
    int i = blockIdx.x;
    int p = g_pos[i];
    if (p < 0) return;
    int e = g_eid[i];
    int n = i & (NTOK - 1);
    const float4 v = ((const float4*)(x + (size_t)n * DDIM))[threadIdx.x];
    __half2* dst = (__half2*)(g_disp + (size_t)(e*CAP + p) * DDIM) + threadIdx.x * 2;
    dst[0] = __floats2half2_rn(v.x, v.y);
    dst[1] = __floats2half2_rn(v.z, v.w);
}

// ---------------- fp16 mma GEMM ----------------
// CTA 128x128, BK=64, 3-stage cp.async, 8 warps (4m x 2n), warp tile 32x64.
// gemm1 (DO_GELU=1, CONV=1): grid.z==NEXP blocks convert w2 (needed only by gemm2).
template<int KDIM, int NDIM, bool DO_GELU, bool CONV, typename OutT>
__global__ void __launch_bounds__(256, 2)
gemm_mma(const __half* __restrict__ Abase, const __half* __restrict__ Bbase,
         const float* __restrict__ biasb, OutT* __restrict__ Cbase,
         const float* __restrict__ Wsrc, __half* __restrict__ Wdst) {
    extern __shared__ char dynsm[];
    int tid = threadIdx.x;

    if (CONV && blockIdx.z == NEXP) {
        int bid = blockIdx.y * gridDim.x + blockIdx.x;   // 0..511
        conv_units(Wsrc, Wdst, bid, 1, tid, 256);
        return;
    }

    uint32_t sbase = (s2u(dynsm) + 1023u) & ~1023u;
    int lane = tid & 31, warp = tid >> 5;
    int e = blockIdx.z;
    int bm = blockIdx.y * 128, bn = blockIdx.x * 128;
    const __half* A = Abase + (size_t)e * CAP * KDIM + (size_t)bm * KDIM;
    const __half* B = Bbase + (size_t)e * KDIM * NDIM + bn;
    const float* bias = biasb + (size_t)e * NDIM + bn;

    constexpr int KT = KDIM / 64;

    int wm = (warp >> 1) * 32;
    int wn = (warp & 1) * 64;
    int r8 = lane & 7, t4 = lane >> 3;

    float acc[2][8][4];
#pragma unroll
    for (int mi = 0; mi < 2; mi++)
#pragma unroll
        for (int ni = 0; ni < 8; ni++)
#pragma unroll
            for (int q = 0; q < 4; q++) acc[mi][ni][q] = 0.f;

    auto load_stage = [&](int kt) {
        uint32_t sa = sbase + (uint32_t)(kt % STAGES) * STAGE_BYTES;
        uint32_t sb = sa + 16384;
        const __half* Ap = A + kt * 64;
        const __half* Bp = B + (size_t)(kt * 64) * NDIM;
#pragma unroll
        for (int i = 0; i < 4; i++) {
            int idx = i * 256 + tid;
            int row = idx >> 3, c = idx & 7;
            cpasync16(sa + (uint32_t)(row * 128 + ((c ^ (row & 7)) << 4)),
                      Ap + (size_t)row * KDIM + c * 8);
        }
#pragma unroll
        for (int i = 0; i < 4; i++) {
            int idx = i * 256 + tid;
            int row = idx >> 4, c = idx & 15;
            cpasync16(sb + (uint32_t)(row * 256 + ((c ^ (row & 7)) << 4)),
                      Bp + (size_t)row * NDIM + c * 8);
        }
    };

#pragma unroll
    for (int kt = 0; kt < STAGES - 1; kt++) { load_stage(kt); cp_commit(); }

    for (int kt = 0; kt < KT; kt++) {
        cp_wait<STAGES - 2>();
        __syncthreads();

        int ktp = kt + STAGES - 1;
        if (ktp < KT) load_stage(ktp);
        cp_commit();

        uint32_t sA = sbase + (uint32_t)(kt % STAGES) * STAGE_BYTES;
        uint32_t sB = sA + 16384;
#pragma unroll
        for (int ks4 = 0; ks4 < 4; ks4++) {
            int kc = ks4 * 2;
            uint32_t a[2][4], b[8][2];
#pragma unroll
            for (int mi = 0; mi < 2; mi++) {
                int row = wm + mi * 16 + (t4 & 1) * 8 + r8;
                int cc  = kc + (t4 >> 1);
                ldsm4(a[mi], sA + (uint32_t)(row * 128 + ((cc ^ (row & 7)) << 4)));
            }
#pragma unroll
            for (int nj = 0; nj < 4; nj++) {
                int krow = ks4 * 16 + (lane & 15);
                int c    = ((wn + nj * 16) >> 3) + (lane >> 4);
                uint32_t q[4];
                ldsm4t(q, sB + (uint32_t)(krow * 256 + ((c ^ (krow & 7)) << 4)));
                b[2*nj][0]   = q[0]; b[2*nj][1]   = q[1];
                b[2*nj+1][0] = q[2]; b[2*nj+1][1] = q[3];
            }
#pragma unroll
            for (int mi = 0; mi < 2; mi++)
#pragma unroll
                for (int ni = 0; ni < 8; ni++)
                    mma16816(acc[mi][ni], a[mi], b[ni]);
        }
    }

    // epilogue
    int grp = lane >> 2, tig = lane & 3;
    OutT* Ce = Cbase + (size_t)e * CAP * NDIM;
#pragma unroll
    for (int mi = 0; mi < 2; mi++) {
#pragma unroll
        for (int ni = 0; ni < 8; ni++) {
            int row = bm + wm + mi * 16 + grp;
            int col = bn + wn + ni * 8 + tig * 2;
            float b0  = bias[wn + ni * 8 + tig * 2];
            float b1v = bias[wn + ni * 8 + tig * 2 + 1];
            float v0 = acc[mi][ni][0] + b0;
            float v1 = acc[mi][ni][1] + b1v;
            float v2 = acc[mi][ni][2] + b0;
            float v3 = acc[mi][ni][3] + b1v;
            if (DO_GELU) {
                v0 = gelu_exact(v0); v1 = gelu_exact(v1);
                v2 = gelu_exact(v2); v3 = gelu_exact(v3);
            }
            if (sizeof(OutT) == 2) {
                *(__half2*)((__half*)Ce + (size_t)row * NDIM + col) = __floats2half2_rn(v0, v1);
                *(__half2*)((__half*)Ce + (size_t)(row + 8) * NDIM + col) = __floats2half2_rn(v2, v3);
            } else {
                *(float2*)((float*)Ce + (size_t)row * NDIM + col) = make_float2(v0, v1);
                *(float2*)((float*)Ce + (size_t)(row + 8) * NDIM + col) = make_float2(v2, v3);
            }
        }
    }
}

// ---------------- combine (gather + gate-weighted sum) ----------------
__global__ void combine_kernel(float* __restrict__ out) {
    int n = blockIdx.x;
    int t = threadIdx.x;
    float4 acc = make_float4(0.f, 0.f, 0.f, 0.f);
#pragma unroll
    for (int kk = 0; kk < 2; kk++) {
        int i = kk * NTOK + n;
        int p = g_pos[i];
        if (p >= 0) {
            float g = g_gv[i];
            const float4 v = *((const float4*)(g_y + (size_t)(g_eid[i]*CAP + p) * DDIM) + t);
            acc.x += g * v.x; acc.y += g * v.y;
            acc.z += g * v.z; acc.w += g * v.w;
        }
    }
    ((float4*)out)[(size_t)n * 256 + t] = acc;
}

// ---------------- launch ----------------
extern "C" void kernel_launch(void* const* d_in, const int* in_sizes, int n_in,
                              void* d_out, int out_size) {
    const float* x  = (const float*)d_in[0];
    const float* wg = (const float*)d_in[1];
    const float* w1 = (const float*)d_in[2];
    const float* b1 = (const float*)d_in[3];
    const float* w2 = (const float*)d_in[4];
    const float* b2 = (const float*)d_in[5];
    float* out = (float*)d_out;

    static int attr_done = 0;
    if (!attr_done) {
        cudaFuncSetAttribute(gemm_mma<DDIM, HDIM, true,  true,  __half>,
                             cudaFuncAttributeMaxDynamicSharedMemorySize, DSMEM_BYTES);
        cudaFuncSetAttribute(gemm_mma<HDIM, DDIM, false, false, float>,
                             cudaFuncAttributeMaxDynamicSharedMemorySize, DSMEM_BYTES);
        attr_done = 1;
    }

    __half* w1h;  cudaGetSymbolAddress((void**)&w1h,  g_w1h);
    __half* w2h;  cudaGetSymbolAddress((void**)&w2h,  g_w2h);
    __half* disp; cudaGetSymbolAddress((void**)&disp, g_disp);
    __half* hbuf; cudaGetSymbolAddress((void**)&hbuf, g_h);
    float*  ybuf; cudaGetSymbolAddress((void**)&ybuf, g_y);

    // w1 convert rides along gate (256 units) and pos (256 units);
    // w2 convert rides along gemm1 (z == NEXP).
    gate_kernel<<<NTOK/8 + GATE_CONV, 256>>>(x, wg, w1);
    pos_kernel<<<1 + POS_CONV_BLOCKS, 1024>>>(w1);
    dispatch_kernel<<<NENT, 256>>>(x);
    gemm_mma<DDIM, HDIM, true, true, __half>
        <<<dim3(HDIM/128, CAP/128, NEXP + 1), 256, DSMEM_BYTES>>>(
        disp, w1h, b1, hbuf, w2, w2h);
    gemm_mma<HDIM, DDIM, false, false, float>
        <<<dim3(DDIM/128, CAP/128, NEXP), 256, DSMEM_BYTES>>>(
        hbuf, w2h, b2, ybuf, nullptr, nullptr);
    combine_kernel<<<NTOK, 256>>>(out);
}